// round 16
// baseline (speedup 1.0000x reference)
#include <cuda_runtime.h>
#include <cuda_bf16.h>
#include <math.h>

#define N_NODES 50000
#define DIM     64
#define NHEAD   8
#define NEDGE   800000
#define NEG_SLOPE 0.2f

#define SCAN_BLK  1024
#define SCAN_NBLK ((N_NODES + SCAN_BLK - 1) / SCAN_BLK)   // 49
#define NPW       4                                        // nodes per warp
#define AGG_WARPS ((N_NODES + NPW - 1) / NPW)              // 12500

// Scratch (device globals). INVARIANT: g_deg zero at module load and re-zeroed
// by fill_kernel each call.
__device__ float g_sdst[N_NODES * NHEAD];
__device__ float g_ssrc[N_NODES * NHEAD];
__device__ int   g_deg[N_NODES];
__device__ int   g_row[N_NODES + 1];
__device__ int   g_cursor[N_NODES];
__device__ int   g_csr_src[NEDGE];
__device__ float g_csr_ex[(size_t)NEDGE * NHEAD];

__device__ __forceinline__ float lrelu(float v) {
    return v >= 0.0f ? v : NEG_SLOPE * v;
}

// ---------------------------------------------------------------------------
// Kernel 1: per-node scores (warp computes 2 nodes) + fused degree histogram.
__global__ void scores_hist_kernel(const float* __restrict__ h_t,
                                   const float* __restrict__ att,
                                   const int* __restrict__ ei) {
    __shared__ float s_att[NHEAD * 2 * DIM];
    for (int i = threadIdx.x; i < NHEAD * 2 * DIM; i += blockDim.x)
        s_att[i] = att[i];
    __syncthreads();

    int idx = blockIdx.x * blockDim.x + threadIdx.x;
    if (idx >= NEDGE) return;

    atomicAdd(&g_deg[ei[NEDGE + idx]], 1);

    int lane = threadIdx.x & 31;
    int half = lane >> 4;
    int sub  = lane & 15;
    int n = (idx >> 5) * 2 + half;

    const float4 x = ((const float4*)(h_t + (size_t)n * DIM))[sub];

    float vals[16];
#pragma unroll
    for (int c = 0; c < 16; c++) {
        const float4 a = *(const float4*)(s_att + (c & 7) * 128 + (c >> 3) * 64 + sub * 4);
        vals[c] = x.x * a.x + x.y * a.y + x.z * a.z + x.w * a.w;
    }
    int cnt = 16;
#pragma unroll
    for (int o = 8; o >= 1; o >>= 1) {
        bool hi = (sub & o) != 0;
        int hc = cnt >> 1;
#pragma unroll
        for (int i = 0; i < 8; i++) {
            if (i < hc) {
                float mine = hi ? vals[i] : vals[i + hc];
                float keep = hi ? vals[i + hc] : vals[i];
                float recv = __shfl_xor_sync(0xffffffffu, mine, o);
                vals[i] = keep + recv;
            }
        }
        cnt = hc;
    }
    if (sub < 8) g_sdst[n * NHEAD + sub]       = vals[0];
    else         g_ssrc[n * NHEAD + (sub - 8)] = vals[0];
}

// ---------------------------------------------------------------------------
// Kernel 2: single-kernel scan; each block self-computes its prefix.
__global__ void scan_kernel() {
    __shared__ int sh[SCAN_BLK];
    __shared__ int red[32];
    __shared__ int s_boff;
    int t = threadIdx.x;
    int bid = blockIdx.x;

    int limit = bid * SCAN_BLK;
    int acc = 0;
    for (int i = t; i < limit; i += SCAN_BLK) acc += g_deg[i];
#pragma unroll
    for (int o = 16; o > 0; o >>= 1)
        acc += __shfl_down_sync(0xffffffffu, acc, o);
    if ((t & 31) == 0) red[t >> 5] = acc;
    __syncthreads();
    if (t < 32) {
        int w = red[t];
#pragma unroll
        for (int o = 16; o > 0; o >>= 1)
            w += __shfl_down_sync(0xffffffffu, w, o);
        if (t == 0) s_boff = w;
    }

    int i = bid * SCAN_BLK + t;
    int d = (i < N_NODES) ? g_deg[i] : 0;
    sh[t] = d;
    __syncthreads();
    for (int o = 1; o < SCAN_BLK; o <<= 1) {
        int u = (t >= o) ? sh[t - o] : 0;
        __syncthreads();
        sh[t] += u;
        __syncthreads();
    }
    if (i < N_NODES) {
        int excl = s_boff + sh[t] - d;
        g_row[i] = excl;
        g_cursor[i] = excl;
    }
    if (i == N_NODES - 1) g_row[N_NODES] = NEDGE;
}

// ---------------------------------------------------------------------------
// Kernel 3: fill CSR + per-edge exp for 8 heads; 4 edges per thread for MLP.
__global__ void fill_kernel(const int* __restrict__ ei) {
    int tid = blockIdx.x * blockDim.x + threadIdx.x;
    if (tid < N_NODES) g_deg[tid] = 0;
    if (tid >= NEDGE / 4) return;

    const int4 src4 = ((const int4*)ei)[tid];
    const int4 dst4 = ((const int4*)(ei + NEDGE))[tid];
    int srcs[4] = {src4.x, src4.y, src4.z, src4.w};
    int dsts[4] = {dst4.x, dst4.y, dst4.z, dst4.w};

    int ps[4];
#pragma unroll
    for (int k = 0; k < 4; k++)
        ps[k] = atomicAdd(&g_cursor[dsts[k]], 1);

    float4 d0[4], d1[4], s0[4], s1[4];
#pragma unroll
    for (int k = 0; k < 4; k++) {
        const float4* pd = (const float4*)(g_sdst + dsts[k] * NHEAD);
        const float4* pp = (const float4*)(g_ssrc + srcs[k] * NHEAD);
        d0[k] = pd[0]; d1[k] = pd[1];
        s0[k] = pp[0]; s1[k] = pp[1];
    }

#pragma unroll
    for (int k = 0; k < 4; k++) {
        float4 e0, e1;
        e0.x = __expf(lrelu(d0[k].x + s0[k].x));
        e0.y = __expf(lrelu(d0[k].y + s0[k].y));
        e0.z = __expf(lrelu(d0[k].z + s0[k].z));
        e0.w = __expf(lrelu(d0[k].w + s0[k].w));
        e1.x = __expf(lrelu(d1[k].x + s1[k].x));
        e1.y = __expf(lrelu(d1[k].y + s1[k].y));
        e1.z = __expf(lrelu(d1[k].z + s1[k].z));
        e1.w = __expf(lrelu(d1[k].w + s1[k].w));
        g_csr_src[ps[k]] = srcs[k];
        float4* pe = (float4*)(g_csr_ex + (size_t)ps[k] * NHEAD);
        pe[0] = e0;
        pe[1] = e1;
    }
}

// ---------------------------------------------------------------------------
// Kernel 4: aggregation + normalize + ELU. Each warp processes NPW=4
// CONSECUTIVE nodes sequentially — warp work = sum of 4 iid degrees, halving
// relative load variance (the prior 1-node/warp layout wasted ~35% of issue
// slots on max-of-degree tails). Per-node body identical to R15: lane owns
// dims {2*lane,2*lane+1} for all 8 heads; MLP-4 batched LDG.64 gathers;
// smem-staged ex.
__global__ void __launch_bounds__(128, 8)
node_agg_kernel(const float* __restrict__ h_t, float* __restrict__ out) {
    __shared__ float s_ex[4][32 * NHEAD];          // 1KB per warp
    int wib  = threadIdx.x >> 5;
    int warp = (blockIdx.x * blockDim.x + threadIdx.x) >> 5;
    if (warp >= AGG_WARPS) return;
    int lane = threadIdx.x & 31;

    const char* hbase = (const char*)h_t + lane * 8;   // + s*256 per edge
    float* exrow = s_ex[wib];

    int n_begin = warp * NPW;
    int n_end   = n_begin + NPW; if (n_end > N_NODES) n_end = N_NODES;

    for (int n = n_begin; n < n_end; n++) {
        int rs = g_row[n];
        int re = g_row[n + 1];

        float2 acc[8];
#pragma unroll
        for (int k = 0; k < 8; k++) acc[k] = make_float2(0.f, 0.f);
        float dsum[8];
#pragma unroll
        for (int k = 0; k < 8; k++) dsum[k] = 0.f;

        for (int base = rs; base < re; base += 32) {
            int cnt = re - base; if (cnt > 32) cnt = 32;

            // stage: lane i loads edge i's src + 8 ex values
            int s = 0;
            float4 exa = make_float4(0.f, 0.f, 0.f, 0.f), exb = exa;
            if (lane < cnt) {
                s = g_csr_src[base + lane];
                const float4* pe = (const float4*)(g_csr_ex + (size_t)(base + lane) * NHEAD);
                exa = pe[0]; exb = pe[1];
            }
            dsum[0] += exa.x; dsum[1] += exa.y; dsum[2] += exa.z; dsum[3] += exa.w;
            dsum[4] += exb.x; dsum[5] += exb.y; dsum[6] += exb.z; dsum[7] += exb.w;

            __syncwarp();
            float4* sw = (float4*)(exrow + lane * NHEAD);
            sw[0] = exa; sw[1] = exb;
            __syncwarp();

            int j = 0;
            for (; j + 4 <= cnt; j += 4) {
                int s0 = __shfl_sync(0xffffffffu, s, j);
                int s1 = __shfl_sync(0xffffffffu, s, j + 1);
                int s2 = __shfl_sync(0xffffffffu, s, j + 2);
                int s3 = __shfl_sync(0xffffffffu, s, j + 3);
                float2 v0 = *(const float2*)(hbase + ((size_t)s0 << 8));
                float2 v1 = *(const float2*)(hbase + ((size_t)s1 << 8));
                float2 v2 = *(const float2*)(hbase + ((size_t)s2 << 8));
                float2 v3 = *(const float2*)(hbase + ((size_t)s3 << 8));

                const float* er = exrow + j * NHEAD;
#pragma unroll
                for (int p = 0; p < 4; p++) {
                    float2 v = (p == 0) ? v0 : (p == 1) ? v1 : (p == 2) ? v2 : v3;
                    float4 e0 = *(const float4*)(er + p * NHEAD);
                    float4 e1 = *(const float4*)(er + p * NHEAD + 4);
                    acc[0].x += e0.x * v.x; acc[0].y += e0.x * v.y;
                    acc[1].x += e0.y * v.x; acc[1].y += e0.y * v.y;
                    acc[2].x += e0.z * v.x; acc[2].y += e0.z * v.y;
                    acc[3].x += e0.w * v.x; acc[3].y += e0.w * v.y;
                    acc[4].x += e1.x * v.x; acc[4].y += e1.x * v.y;
                    acc[5].x += e1.y * v.x; acc[5].y += e1.y * v.y;
                    acc[6].x += e1.z * v.x; acc[6].y += e1.z * v.y;
                    acc[7].x += e1.w * v.x; acc[7].y += e1.w * v.y;
                }
            }
            for (; j < cnt; j++) {
                int sj = __shfl_sync(0xffffffffu, s, j);
                float4 e0 = *(const float4*)(exrow + j * NHEAD);
                float4 e1 = *(const float4*)(exrow + j * NHEAD + 4);
                float2 v = *(const float2*)(hbase + ((size_t)sj << 8));
                acc[0].x += e0.x * v.x; acc[0].y += e0.x * v.y;
                acc[1].x += e0.y * v.x; acc[1].y += e0.y * v.y;
                acc[2].x += e0.z * v.x; acc[2].y += e0.z * v.y;
                acc[3].x += e0.w * v.x; acc[3].y += e0.w * v.y;
                acc[4].x += e1.x * v.x; acc[4].y += e1.x * v.y;
                acc[5].x += e1.y * v.x; acc[5].y += e1.y * v.y;
                acc[6].x += e1.z * v.x; acc[6].y += e1.z * v.y;
                acc[7].x += e1.w * v.x; acc[7].y += e1.w * v.y;
            }
        }

        // denom: butterfly-reduce the 8 partials across all 32 lanes
#pragma unroll
        for (int o = 16; o > 0; o >>= 1) {
#pragma unroll
            for (int k = 0; k < 8; k++)
                dsum[k] += __shfl_xor_sync(0xffffffffu, dsum[k], o);
        }

        bool nz = (re > rs);
        float* orow = out + (size_t)n * (NHEAD * DIM) + lane * 2;
#pragma unroll
        for (int k = 0; k < 8; k++) {
            float inv = nz ? 1.0f / dsum[k] : 0.f;   // zero-degree -> zeros
            float vx = acc[k].x * inv;
            float vy = acc[k].y * inv;
            vx = vx > 0.f ? vx : (__expf(vx) - 1.0f);
            vy = vy > 0.f ? vy : (__expf(vy) - 1.0f);
            *(float2*)(orow + k * DIM) = make_float2(vx, vy);
        }
    }
}

// ---------------------------------------------------------------------------
extern "C" void kernel_launch(void* const* d_in, const int* in_sizes, int n_in,
                              void* d_out, int out_size) {
    const float* h_t = (const float*)d_in[0];
    const int*   ei  = (const int*)d_in[1];
    const float* att = (const float*)d_in[2];
    float*       out = (float*)d_out;

    scores_hist_kernel<<<(NEDGE + 255) / 256, 256>>>(h_t, att, ei);  // 1
    scan_kernel<<<SCAN_NBLK, SCAN_BLK>>>();                          // 2
    fill_kernel<<<(NEDGE / 4 + 255) / 256, 256>>>(ei);               // 3
    int blocks = (AGG_WARPS * 32 + 127) / 128;
    node_agg_kernel<<<blocks, 128>>>(h_t, out);                      // 4 (ncu)
}

// round 17
// speedup vs baseline: 1.0862x; 1.0862x over previous
#include <cuda_runtime.h>
#include <cuda_bf16.h>
#include <math.h>

#define N_NODES 50000
#define DIM     64
#define NHEAD   8
#define NEDGE   800000
#define NEG_SLOPE 0.2f

#define SCAN_BLK  1024
#define SCAN_NBLK ((N_NODES + SCAN_BLK - 1) / SCAN_BLK)   // 49

// Scratch (device globals). INVARIANT: g_deg zero at module load and re-zeroed
// by fill_kernel each call.
__device__ float g_sdst[N_NODES * NHEAD];
__device__ float g_ssrc[N_NODES * NHEAD];
__device__ int   g_deg[N_NODES];
__device__ int   g_row[N_NODES + 1];
__device__ int   g_cursor[N_NODES];
__device__ int   g_csr_src[NEDGE];

__device__ __forceinline__ float lrelu(float v) {
    return v >= 0.0f ? v : NEG_SLOPE * v;
}

// ---------------------------------------------------------------------------
// Kernel 1: per-node scores (warp computes 2 nodes) + fused degree histogram.
__global__ void scores_hist_kernel(const float* __restrict__ h_t,
                                   const float* __restrict__ att,
                                   const int* __restrict__ ei) {
    __shared__ float s_att[NHEAD * 2 * DIM];
    for (int i = threadIdx.x; i < NHEAD * 2 * DIM; i += blockDim.x)
        s_att[i] = att[i];
    __syncthreads();

    int idx = blockIdx.x * blockDim.x + threadIdx.x;
    if (idx >= NEDGE) return;

    atomicAdd(&g_deg[ei[NEDGE + idx]], 1);

    int lane = threadIdx.x & 31;
    int half = lane >> 4;
    int sub  = lane & 15;
    int n = (idx >> 5) * 2 + half;

    const float4 x = ((const float4*)(h_t + (size_t)n * DIM))[sub];

    float vals[16];
#pragma unroll
    for (int c = 0; c < 16; c++) {
        const float4 a = *(const float4*)(s_att + (c & 7) * 128 + (c >> 3) * 64 + sub * 4);
        vals[c] = x.x * a.x + x.y * a.y + x.z * a.z + x.w * a.w;
    }
    int cnt = 16;
#pragma unroll
    for (int o = 8; o >= 1; o >>= 1) {
        bool hi = (sub & o) != 0;
        int hc = cnt >> 1;
#pragma unroll
        for (int i = 0; i < 8; i++) {
            if (i < hc) {
                float mine = hi ? vals[i] : vals[i + hc];
                float keep = hi ? vals[i + hc] : vals[i];
                float recv = __shfl_xor_sync(0xffffffffu, mine, o);
                vals[i] = keep + recv;
            }
        }
        cnt = hc;
    }
    if (sub < 8) g_sdst[n * NHEAD + sub]       = vals[0];
    else         g_ssrc[n * NHEAD + (sub - 8)] = vals[0];
}

// ---------------------------------------------------------------------------
// Kernel 2: single-kernel scan; each block self-computes its prefix.
__global__ void scan_kernel() {
    __shared__ int sh[SCAN_BLK];
    __shared__ int red[32];
    __shared__ int s_boff;
    int t = threadIdx.x;
    int bid = blockIdx.x;

    int limit = bid * SCAN_BLK;
    int acc = 0;
    for (int i = t; i < limit; i += SCAN_BLK) acc += g_deg[i];
#pragma unroll
    for (int o = 16; o > 0; o >>= 1)
        acc += __shfl_down_sync(0xffffffffu, acc, o);
    if ((t & 31) == 0) red[t >> 5] = acc;
    __syncthreads();
    if (t < 32) {
        int w = red[t];
#pragma unroll
        for (int o = 16; o > 0; o >>= 1)
            w += __shfl_down_sync(0xffffffffu, w, o);
        if (t == 0) s_boff = w;
    }

    int i = bid * SCAN_BLK + t;
    int d = (i < N_NODES) ? g_deg[i] : 0;
    sh[t] = d;
    __syncthreads();
    for (int o = 1; o < SCAN_BLK; o <<= 1) {
        int u = (t >= o) ? sh[t - o] : 0;
        __syncthreads();
        sh[t] += u;
        __syncthreads();
    }
    if (i < N_NODES) {
        int excl = s_boff + sh[t] - d;
        g_row[i] = excl;
        g_cursor[i] = excl;
    }
    if (i == N_NODES - 1) g_row[N_NODES] = NEDGE;
}

// ---------------------------------------------------------------------------
// Kernel 3: fill CSR only (no gathers, no exp — those moved into node_agg's
// staging phase). 4 edges per thread; re-zeroes g_deg for the next call.
__global__ void fill_kernel(const int* __restrict__ ei) {
    int tid = blockIdx.x * blockDim.x + threadIdx.x;
    if (tid < N_NODES) g_deg[tid] = 0;
    if (tid >= NEDGE / 4) return;

    const int4 src4 = ((const int4*)ei)[tid];
    const int4 dst4 = ((const int4*)(ei + NEDGE))[tid];
    int srcs[4] = {src4.x, src4.y, src4.z, src4.w};
    int dsts[4] = {dst4.x, dst4.y, dst4.z, dst4.w};

#pragma unroll
    for (int k = 0; k < 4; k++) {
        int p = atomicAdd(&g_cursor[dsts[k]], 1);
        g_csr_src[p] = srcs[k];
    }
}

// ---------------------------------------------------------------------------
// Kernel 4: aggregation + softmax + ELU. One warp per node (R15 structure).
// Staging phase now COMPUTES ex: lane i gathers ssrc[src_i] (32B), adds the
// node's register-resident sdst, lrelu+__expf (8 MUFU/chunk-lane), stages to
// smem. Inner loop unchanged: MLP-4 batched LDG.64 feature gathers + 2
// broadcast LDS.128 + 16 FMA per edge.
__global__ void __launch_bounds__(128, 8)
node_agg_kernel(const float* __restrict__ h_t, float* __restrict__ out) {
    __shared__ float s_ex[4][32 * NHEAD];          // 1KB per warp
    int wib  = threadIdx.x >> 5;
    int warp = (blockIdx.x * blockDim.x + threadIdx.x) >> 5;
    if (warp >= N_NODES) return;
    int lane = threadIdx.x & 31;
    int n = warp;
    int rs = g_row[n];
    int re = g_row[n + 1];

    const char* hbase = (const char*)h_t + lane * 8;   // + s*256 per edge
    float* exrow = s_ex[wib];

    // node's dst scores, broadcast-loaded once (L1/L2 cached)
    const float4* psd = (const float4*)(g_sdst + n * NHEAD);
    float4 sd0 = psd[0], sd1 = psd[1];

    float2 acc[8];
#pragma unroll
    for (int k = 0; k < 8; k++) acc[k] = make_float2(0.f, 0.f);
    float dsum[8];
#pragma unroll
    for (int k = 0; k < 8; k++) dsum[k] = 0.f;

    for (int base = rs; base < re; base += 32) {
        int cnt = re - base; if (cnt > 32) cnt = 32;

        // stage: lane i loads edge i's src, gathers its ssrc, computes ex
        int s = 0;
        float4 exa = make_float4(0.f, 0.f, 0.f, 0.f), exb = exa;
        if (lane < cnt) {
            s = g_csr_src[base + lane];
            const float4* pss = (const float4*)(g_ssrc + s * NHEAD);
            float4 ss0 = pss[0], ss1 = pss[1];
            exa.x = __expf(lrelu(sd0.x + ss0.x));
            exa.y = __expf(lrelu(sd0.y + ss0.y));
            exa.z = __expf(lrelu(sd0.z + ss0.z));
            exa.w = __expf(lrelu(sd0.w + ss0.w));
            exb.x = __expf(lrelu(sd1.x + ss1.x));
            exb.y = __expf(lrelu(sd1.y + ss1.y));
            exb.z = __expf(lrelu(sd1.z + ss1.z));
            exb.w = __expf(lrelu(sd1.w + ss1.w));
        }
        dsum[0] += exa.x; dsum[1] += exa.y; dsum[2] += exa.z; dsum[3] += exa.w;
        dsum[4] += exb.x; dsum[5] += exb.y; dsum[6] += exb.z; dsum[7] += exb.w;

        __syncwarp();
        float4* sw = (float4*)(exrow + lane * NHEAD);
        sw[0] = exa; sw[1] = exb;
        __syncwarp();

        int j = 0;
        for (; j + 4 <= cnt; j += 4) {
            int s0 = __shfl_sync(0xffffffffu, s, j);
            int s1 = __shfl_sync(0xffffffffu, s, j + 1);
            int s2 = __shfl_sync(0xffffffffu, s, j + 2);
            int s3 = __shfl_sync(0xffffffffu, s, j + 3);
            float2 v0 = *(const float2*)(hbase + ((size_t)s0 << 8));
            float2 v1 = *(const float2*)(hbase + ((size_t)s1 << 8));
            float2 v2 = *(const float2*)(hbase + ((size_t)s2 << 8));
            float2 v3 = *(const float2*)(hbase + ((size_t)s3 << 8));

            const float* er = exrow + j * NHEAD;
#pragma unroll
            for (int p = 0; p < 4; p++) {
                float2 v = (p == 0) ? v0 : (p == 1) ? v1 : (p == 2) ? v2 : v3;
                float4 e0 = *(const float4*)(er + p * NHEAD);
                float4 e1 = *(const float4*)(er + p * NHEAD + 4);
                acc[0].x += e0.x * v.x; acc[0].y += e0.x * v.y;
                acc[1].x += e0.y * v.x; acc[1].y += e0.y * v.y;
                acc[2].x += e0.z * v.x; acc[2].y += e0.z * v.y;
                acc[3].x += e0.w * v.x; acc[3].y += e0.w * v.y;
                acc[4].x += e1.x * v.x; acc[4].y += e1.x * v.y;
                acc[5].x += e1.y * v.x; acc[5].y += e1.y * v.y;
                acc[6].x += e1.z * v.x; acc[6].y += e1.z * v.y;
                acc[7].x += e1.w * v.x; acc[7].y += e1.w * v.y;
            }
        }
        for (; j < cnt; j++) {
            int sj = __shfl_sync(0xffffffffu, s, j);
            float4 e0 = *(const float4*)(exrow + j * NHEAD);
            float4 e1 = *(const float4*)(exrow + j * NHEAD + 4);
            float2 v = *(const float2*)(hbase + ((size_t)sj << 8));
            acc[0].x += e0.x * v.x; acc[0].y += e0.x * v.y;
            acc[1].x += e0.y * v.x; acc[1].y += e0.y * v.y;
            acc[2].x += e0.z * v.x; acc[2].y += e0.z * v.y;
            acc[3].x += e0.w * v.x; acc[3].y += e0.w * v.y;
            acc[4].x += e1.x * v.x; acc[4].y += e1.x * v.y;
            acc[5].x += e1.y * v.x; acc[5].y += e1.y * v.y;
            acc[6].x += e1.z * v.x; acc[6].y += e1.z * v.y;
            acc[7].x += e1.w * v.x; acc[7].y += e1.w * v.y;
        }
    }

    // denom: butterfly-reduce the 8 partials across all 32 lanes
#pragma unroll
    for (int o = 16; o > 0; o >>= 1) {
#pragma unroll
        for (int k = 0; k < 8; k++)
            dsum[k] += __shfl_xor_sync(0xffffffffu, dsum[k], o);
    }

    bool nz = (re > rs);
    float* orow = out + (size_t)n * (NHEAD * DIM) + lane * 2;
#pragma unroll
    for (int k = 0; k < 8; k++) {
        float inv = nz ? 1.0f / dsum[k] : 0.f;      // zero-degree -> zeros
        float vx = acc[k].x * inv;
        float vy = acc[k].y * inv;
        vx = vx > 0.f ? vx : (__expf(vx) - 1.0f);
        vy = vy > 0.f ? vy : (__expf(vy) - 1.0f);
        *(float2*)(orow + k * DIM) = make_float2(vx, vy);
    }
}

// ---------------------------------------------------------------------------
extern "C" void kernel_launch(void* const* d_in, const int* in_sizes, int n_in,
                              void* d_out, int out_size) {
    const float* h_t = (const float*)d_in[0];
    const int*   ei  = (const int*)d_in[1];
    const float* att = (const float*)d_in[2];
    float*       out = (float*)d_out;

    scores_hist_kernel<<<(NEDGE + 255) / 256, 256>>>(h_t, att, ei);  // 1
    scan_kernel<<<SCAN_NBLK, SCAN_BLK>>>();                          // 2
    fill_kernel<<<(NEDGE / 4 + 255) / 256, 256>>>(ei);               // 3
    int blocks = (N_NODES * 32 + 127) / 128;
    node_agg_kernel<<<blocks, 128>>>(h_t, out);                      // 4 (ncu)
}